// round 4
// baseline (speedup 1.0000x reference)
#include <cuda_runtime.h>
#include <cuda_bf16.h>
#include <cstdint>
#include <cstddef>

// ---------------- problem constants ----------------
#define BB     32
#define CIN    192
#define HH     56
#define WWD    56
#define HP     58
#define WP     58
#define COUTN  192
#define KDIM   1728          // CIN * 9
#define HWN    3136          // 56*56
#define NPIX   100352        // BB*HWN

// ---------------- tiling ----------------
#define MTILE   128                // pixels per CTA
#define NBLK    (NPIX / MTILE)     // 784 exactly
#define KC      64                 // K halves per chunk (128 B rows)
#define NCHUNK  27                 // 1728 / 64

// smem stage layout (bytes, relative to stage base; stage base 1024-aligned)
#define A_HI    0                  // 128 x 128B = 16 KB
#define A_LO    16384
#define B_HI    32768              // 192 x 128B = 24 KB
#define B_LO    57344
#define STAGE_BYTES 81920          // 80 KB
#define SMEM_HDR    1024           // bias lives at [0..768)
#define SMEM_TOTAL  (SMEM_HDR + 2 * STAGE_BYTES)   // 164864

// ---------------- device scratch (zero-initialized at module load; ----------------
// padded borders of x are never written -> stay zero, deterministic)
__device__ __align__(16) __nv_bfloat16 g_xhi[(size_t)BB * HP * WP * CIN];
__device__ __align__(16) __nv_bfloat16 g_xlo[(size_t)BB * HP * WP * CIN];
__device__ __align__(16) __nv_bfloat16 g_whi[(size_t)COUTN * KDIM];
__device__ __align__(16) __nv_bfloat16 g_wlo[(size_t)COUTN * KDIM];

// ---------------- helpers ----------------
__device__ __forceinline__ uint32_t smem_u32(const void* p) {
    uint32_t a;
    asm("{ .reg .u64 t; cvta.to.shared.u64 t, %1; cvt.u32.u64 %0, t; }" : "=r"(a) : "l"(p));
    return a;
}

__device__ __forceinline__ uint32_t sw128(uint32_t off) {
    return off ^ ((off >> 3) & 0x70);
}

__device__ __forceinline__ void cpa16(uint32_t dst, const void* src) {
    asm volatile("cp.async.cg.shared.global [%0], [%1], 16;" :: "r"(dst), "l"(src) : "memory");
}

#define CP_COMMIT()  asm volatile("cp.async.commit_group;" ::: "memory")
#define CP_WAIT(N)   asm volatile("cp.async.wait_group %0;" :: "n"(N) : "memory")

__device__ __forceinline__ void ldsm4(uint32_t* r, uint32_t addr) {
    asm volatile("ldmatrix.sync.aligned.m8n8.x4.shared.b16 {%0,%1,%2,%3}, [%4];"
                 : "=r"(r[0]), "=r"(r[1]), "=r"(r[2]), "=r"(r[3]) : "r"(addr));
}

__device__ __forceinline__ void mma_bf16(float* c, const uint32_t* a, const uint32_t* b) {
    asm volatile(
        "mma.sync.aligned.m16n8k16.row.col.f32.bf16.bf16.f32 "
        "{%0,%1,%2,%3}, {%4,%5,%6,%7}, {%8,%9}, {%0,%1,%2,%3};"
        : "+f"(c[0]), "+f"(c[1]), "+f"(c[2]), "+f"(c[3])
        : "r"(a[0]), "r"(a[1]), "r"(a[2]), "r"(a[3]), "r"(b[0]), "r"(b[1]));
}

// ---------------- prep kernel 1: weights -> bf16 hi/lo, K reordered ----------------
// new K index kn = (i*3+j)*192 + c ; old k = c*9 + (i*3+j)
__global__ void prep_w_kernel(const float* __restrict__ w) {
    int idx = blockIdx.x * 256 + threadIdx.x;
    if (idx >= COUTN * KDIM) return;
    int o  = idx / KDIM;
    int kn = idx - o * KDIM;
    int r  = kn / CIN;
    int c  = kn - r * CIN;
    float v = w[o * KDIM + c * 9 + r];
    __nv_bfloat16 hi = __float2bfloat16(v);
    float lo = v - __bfloat162float(hi);
    g_whi[idx] = hi;
    g_wlo[idx] = __float2bfloat16(lo);
}

// ---------------- prep kernel 2: x NCHW fp32 -> NHWC padded bf16 hi/lo ----------------
__global__ void prep_x_kernel(const float* __restrict__ x) {
    __shared__ float tile[32][33];
    int b   = blockIdx.z;
    int hw0 = blockIdx.x * 32;
    int c0  = blockIdx.y * 32;
    int tx  = threadIdx.x & 31;
    int ty  = threadIdx.x >> 5;   // 0..7

    const float* src = x + ((size_t)b * CIN + c0) * HWN + hw0;
#pragma unroll
    for (int r = 0; r < 4; r++)
        tile[ty + r * 8][tx] = src[(size_t)(ty + r * 8) * HWN + tx];
    __syncthreads();

#pragma unroll
    for (int r = 0; r < 4; r++) {
        int hw = hw0 + ty + r * 8;
        int h  = hw / WWD;
        int w  = hw - h * WWD;
        float v = tile[tx][ty + r * 8];
        __nv_bfloat16 hi = __float2bfloat16(v);
        float lo = v - __bfloat162float(hi);
        size_t dst = (((size_t)b * HP + (h + 1)) * WP + (w + 1)) * CIN + c0 + tx;
        g_xhi[dst] = hi;
        g_xlo[dst] = __float2bfloat16(lo);
    }
}

// ---------------- main kernel: im2col GEMM via mma.sync (HMMA) ----------------
// CTA: 128 pixels x 192 couts, 8 warps = 2(M) x 4(N), warp tile 64x48.
// 3-term bf16 split accumulated into one fp32 accumulator set.
__global__ void __launch_bounds__(256, 1)
conv_main_kernel(const float* __restrict__ bias, float* __restrict__ out) {
    extern __shared__ __align__(1024) char smem[];
    uint32_t su = smem_u32(smem);
    int tid  = threadIdx.x;
    int lane = tid & 31;
    int wid  = tid >> 5;
    int blk  = blockIdx.x;

    float* s_bias = (float*)smem;
    if (tid < COUTN) s_bias[tid] = bias[tid];

    // ---- per-thread cp.async geometry ----
    int vr = tid & 7;     // 16B chunk within a 128B row
    int r0 = tid >> 3;    // 0..31 row slot
    int rbase[4];
#pragma unroll
    for (int it = 0; it < 4; it++) {
        int p   = blk * MTILE + r0 + it * 32;
        int b   = p / HWN;
        int rem = p - b * HWN;
        int h   = rem / WWD;
        int w   = rem - h * WWD;
        rbase[it] = ((b * HP + h) * WP + w) * CIN;
    }

    auto issue = [&](int u, int stage) {
        int ij = u / 3;
        int c0 = (u - ij * 3) * KC;
        int i  = ij / 3;
        int j  = ij - i * 3;
        int coff = (i * WP + j) * CIN + c0;
        uint32_t sb = su + SMEM_HDR + (uint32_t)stage * STAGE_BYTES;
        // A: 128 rows x 128B (hi + lo)
#pragma unroll
        for (int it = 0; it < 4; it++) {
            int m = r0 + it * 32;
            uint32_t sw = sw128((uint32_t)m * 128 + vr * 16);
            int go = rbase[it] + coff + vr * 8;
            cpa16(sb + A_HI + sw, g_xhi + go);
            cpa16(sb + A_LO + sw, g_xlo + go);
        }
        // B: 192 rows x 128B (hi + lo)
#pragma unroll
        for (int it = 0; it < 6; it++) {
            int o = r0 + it * 32;
            uint32_t sw = sw128((uint32_t)o * 128 + vr * 16);
            size_t go = (size_t)o * KDIM + u * KC + vr * 8;
            cpa16(sb + B_HI + sw, g_whi + go);
            cpa16(sb + B_LO + sw, g_wlo + go);
        }
    };

    // ---- per-thread mma geometry ----
    int wm = (wid >> 2) * 64;      // warp M offset within CTA tile
    int wn = (wid & 3) * 48;       // warp N offset
    int a_r = lane & 15;
    int a_k = (lane >> 4) * 16;    // bytes
    int b_r = (lane & 7) + ((lane >> 4) << 3);
    int b_k = ((lane >> 3) & 1) * 16;

    float acc[4][6][4];
#pragma unroll
    for (int mt = 0; mt < 4; mt++)
#pragma unroll
        for (int nt = 0; nt < 6; nt++)
#pragma unroll
            for (int q = 0; q < 4; q++) acc[mt][nt][q] = 0.0f;

    // ---- pipelined mainloop (2 smem stages) ----
    issue(0, 0);
    CP_COMMIT();

    for (int u = 0; u < NCHUNK; u++) {
        if (u + 1 < NCHUNK) issue(u + 1, (u + 1) & 1);
        CP_COMMIT();
        CP_WAIT(1);                 // chunk u resident
        __syncthreads();

        uint32_t sb = su + SMEM_HDR + (uint32_t)(u & 1) * STAGE_BYTES;
#pragma unroll
        for (int ks = 0; ks < 4; ks++) {
            uint32_t ahi[4][4], alo[4][4], bhi[3][4], blo[3][4];
            uint32_t kb = (uint32_t)ks * 32;
#pragma unroll
            for (int mt = 0; mt < 4; mt++) {
                uint32_t off = (uint32_t)(wm + mt * 16 + a_r) * 128 + kb + a_k;
                ldsm4(ahi[mt], sb + A_HI + sw128(off));
            }
#pragma unroll
            for (int nb = 0; nb < 3; nb++) {
                uint32_t off = (uint32_t)(wn + nb * 16 + b_r) * 128 + kb + b_k;
                ldsm4(bhi[nb], sb + B_HI + sw128(off));
            }
            // hi * hi
#pragma unroll
            for (int mt = 0; mt < 4; mt++)
#pragma unroll
                for (int nt = 0; nt < 6; nt++)
                    mma_bf16(acc[mt][nt], ahi[mt], &bhi[nt >> 1][(nt & 1) * 2]);
            // hi * lo  (reuse A_hi fragments)
#pragma unroll
            for (int nb = 0; nb < 3; nb++) {
                uint32_t off = (uint32_t)(wn + nb * 16 + b_r) * 128 + kb + b_k;
                ldsm4(blo[nb], sb + B_LO + sw128(off));
            }
#pragma unroll
            for (int mt = 0; mt < 4; mt++)
#pragma unroll
                for (int nt = 0; nt < 6; nt++)
                    mma_bf16(acc[mt][nt], ahi[mt], &blo[nt >> 1][(nt & 1) * 2]);
            // lo * hi  (reuse B_hi fragments)
#pragma unroll
            for (int mt = 0; mt < 4; mt++) {
                uint32_t off = (uint32_t)(wm + mt * 16 + a_r) * 128 + kb + a_k;
                ldsm4(alo[mt], sb + A_LO + sw128(off));
            }
#pragma unroll
            for (int mt = 0; mt < 4; mt++)
#pragma unroll
                for (int nt = 0; nt < 6; nt++)
                    mma_bf16(acc[mt][nt], alo[mt], &bhi[nt >> 1][(nt & 1) * 2]);
        }
        __syncthreads();
    }

    // ---- epilogue: out[b][cout][hw] = acc + bias ----
    int pix0 = blk * MTILE + wm;
#pragma unroll
    for (int mt = 0; mt < 4; mt++) {
#pragma unroll
        for (int half = 0; half < 2; half++) {
            int p   = pix0 + mt * 16 + half * 8 + (lane >> 2);
            int b   = p / HWN;
            int hw  = p - b * HWN;
            float* ob = out + (size_t)b * COUTN * HWN + hw;
#pragma unroll
            for (int nt = 0; nt < 6; nt++) {
                int n = wn + nt * 8 + (lane & 3) * 2;
                ob[(size_t)n * HWN]       = acc[mt][nt][half * 2 + 0] + s_bias[n];
                ob[(size_t)(n + 1) * HWN] = acc[mt][nt][half * 2 + 1] + s_bias[n + 1];
            }
        }
    }
}

// ---------------- launch ----------------
extern "C" void kernel_launch(void* const* d_in, const int* in_sizes, int n_in,
                              void* d_out, int out_size) {
    const float* x    = (const float*)d_in[0];
    const float* w    = (const float*)d_in[1];
    const float* bias = (const float*)d_in[2];
    float* out        = (float*)d_out;
    (void)in_sizes; (void)n_in; (void)out_size;

    cudaFuncSetAttribute(conv_main_kernel,
                         cudaFuncAttributeMaxDynamicSharedMemorySize, SMEM_TOTAL);

    prep_w_kernel<<<(COUTN * KDIM + 255) / 256, 256>>>(w);
    prep_x_kernel<<<dim3(HWN / 32, CIN / 32, BB), 256>>>(x);
    conv_main_kernel<<<NBLK, 256, SMEM_TOTAL>>>(bias, out);
}

// round 5
// speedup vs baseline: 1.4576x; 1.4576x over previous
#include <cuda_runtime.h>
#include <cuda_fp16.h>
#include <cstdint>
#include <cstddef>

// ---------------- problem constants ----------------
#define BB     32
#define CIN    192
#define HH     56
#define WWD    56
#define HP     58
#define WP     58
#define COUTN  192
#define KDIM   1728          // CIN * 9
#define HWN    3136          // 56*56
#define NPIX   100352        // BB*HWN

// ---------------- tiling ----------------
#define MTILE   128                // pixels per CTA
#define NBLK    (NPIX / MTILE)     // 784 exactly
#define KC      64                 // K halves per chunk (128 B rows)
#define NCHUNK  27                 // 1728 / 64
#define NSTAGE  3

// smem stage layout (bytes, relative to stage base; stage base 1024-aligned)
#define A_HI    0                  // 128 x 128B = 16 KB
#define B_HI    16384              // 192 x 128B = 24 KB
#define B_LO    40960              // 192 x 128B = 24 KB
#define STAGE_BYTES 65536          // 64 KB
#define SMEM_HDR    1024           // bias lives at [0..768)
#define SMEM_TOTAL  (SMEM_HDR + NSTAGE * STAGE_BYTES)   // 197632

// ---------------- device scratch (zero-initialized at module load; ----------------
// padded borders of x are never written -> stay zero, deterministic)
__device__ __align__(16) __half g_xhi[(size_t)BB * HP * WP * CIN];
__device__ __align__(16) __half g_whi[(size_t)COUTN * KDIM];
__device__ __align__(16) __half g_wlo[(size_t)COUTN * KDIM];

// ---------------- helpers ----------------
__device__ __forceinline__ uint32_t smem_u32(const void* p) {
    uint32_t a;
    asm("{ .reg .u64 t; cvta.to.shared.u64 t, %1; cvt.u32.u64 %0, t; }" : "=r"(a) : "l"(p));
    return a;
}

__device__ __forceinline__ uint32_t sw128(uint32_t off) {
    return off ^ ((off >> 3) & 0x70);
}

__device__ __forceinline__ void cpa16(uint32_t dst, const void* src) {
    asm volatile("cp.async.cg.shared.global [%0], [%1], 16;" :: "r"(dst), "l"(src) : "memory");
}

#define CP_COMMIT()  asm volatile("cp.async.commit_group;" ::: "memory")
#define CP_WAIT(N)   asm volatile("cp.async.wait_group %0;" :: "n"(N) : "memory")

__device__ __forceinline__ void ldsm4(uint32_t* r, uint32_t addr) {
    asm volatile("ldmatrix.sync.aligned.m8n8.x4.shared.b16 {%0,%1,%2,%3}, [%4];"
                 : "=r"(r[0]), "=r"(r[1]), "=r"(r[2]), "=r"(r[3]) : "r"(addr));
}

__device__ __forceinline__ void mma_f16(float* c, const uint32_t* a, const uint32_t* b) {
    asm volatile(
        "mma.sync.aligned.m16n8k16.row.col.f32.f16.f16.f32 "
        "{%0,%1,%2,%3}, {%4,%5,%6,%7}, {%8,%9}, {%0,%1,%2,%3};"
        : "+f"(c[0]), "+f"(c[1]), "+f"(c[2]), "+f"(c[3])
        : "r"(a[0]), "r"(a[1]), "r"(a[2]), "r"(a[3]), "r"(b[0]), "r"(b[1]));
}

// ---------------- prep kernel 1: weights -> fp16 hi/lo, K reordered ----------------
// new K index kn = (i*3+j)*192 + c ; old k = c*9 + (i*3+j)
__global__ void prep_w_kernel(const float* __restrict__ w) {
    int idx = blockIdx.x * 256 + threadIdx.x;
    if (idx >= COUTN * KDIM) return;
    int o  = idx / KDIM;
    int kn = idx - o * KDIM;
    int r  = kn / CIN;
    int c  = kn - r * CIN;
    float v = w[o * KDIM + c * 9 + r];
    __half hi = __float2half_rn(v);
    float lo = v - __half2float(hi);
    g_whi[idx] = hi;
    g_wlo[idx] = __float2half_rn(lo);
}

// ---------------- prep kernel 2: x NCHW fp32 -> NHWC padded fp16 ----------------
__global__ void prep_x_kernel(const float* __restrict__ x) {
    __shared__ float tile[32][33];
    int b   = blockIdx.z;
    int hw0 = blockIdx.x * 32;
    int c0  = blockIdx.y * 32;
    int tx  = threadIdx.x & 31;
    int ty  = threadIdx.x >> 5;   // 0..7

    const float* src = x + ((size_t)b * CIN + c0) * HWN + hw0;
#pragma unroll
    for (int r = 0; r < 4; r++)
        tile[ty + r * 8][tx] = src[(size_t)(ty + r * 8) * HWN + tx];
    __syncthreads();

#pragma unroll
    for (int r = 0; r < 4; r++) {
        int hw = hw0 + ty + r * 8;
        int h  = hw / WWD;
        int w  = hw - h * WWD;
        float v = tile[tx][ty + r * 8];
        size_t dst = (((size_t)b * HP + (h + 1)) * WP + (w + 1)) * CIN + c0 + tx;
        g_xhi[dst] = __float2half_rn(v);
    }
}

// ---------------- main kernel: im2col GEMM via mma.sync (HMMA fp16) ----------------
// CTA: 128 pixels x 192 couts, 8 warps = 2(M) x 4(N), warp tile 64x48.
// 2-term fp16 split: out = x_hi*w_hi + x_hi*w_lo   (fp32 accumulate)
__global__ void __launch_bounds__(256, 1)
conv_main_kernel(const float* __restrict__ bias, float* __restrict__ out) {
    extern __shared__ __align__(1024) char smem[];
    uint32_t su = smem_u32(smem);
    int tid  = threadIdx.x;
    int lane = tid & 31;
    int wid  = tid >> 5;
    int blk  = blockIdx.x;

    float* s_bias = (float*)smem;
    if (tid < COUTN) s_bias[tid] = bias[tid];

    // ---- per-thread cp.async geometry ----
    int vr = tid & 7;     // 16B chunk within a 128B row
    int r0 = tid >> 3;    // 0..31 row slot
    int rbase[4];
#pragma unroll
    for (int it = 0; it < 4; it++) {
        int p   = blk * MTILE + r0 + it * 32;
        int b   = p / HWN;
        int rem = p - b * HWN;
        int h   = rem / WWD;
        int w   = rem - h * WWD;
        rbase[it] = ((b * HP + h) * WP + w) * CIN;
    }

    auto issue = [&](int u, int stage) {
        int ij = u / 3;
        int c0 = (u - ij * 3) * KC;
        int i  = ij / 3;
        int j  = ij - i * 3;
        int coff = (i * WP + j) * CIN + c0;
        uint32_t sb = su + SMEM_HDR + (uint32_t)stage * STAGE_BYTES;
        // A: 128 rows x 128B (hi only)
#pragma unroll
        for (int it = 0; it < 4; it++) {
            int m = r0 + it * 32;
            uint32_t sw = sw128((uint32_t)m * 128 + vr * 16);
            int go = rbase[it] + coff + vr * 8;
            cpa16(sb + A_HI + sw, g_xhi + go);
        }
        // B: 192 rows x 128B (hi + lo)
#pragma unroll
        for (int it = 0; it < 6; it++) {
            int o = r0 + it * 32;
            uint32_t sw = sw128((uint32_t)o * 128 + vr * 16);
            size_t go = (size_t)o * KDIM + u * KC + vr * 8;
            cpa16(sb + B_HI + sw, g_whi + go);
            cpa16(sb + B_LO + sw, g_wlo + go);
        }
    };

    // ---- per-thread mma geometry ----
    int wm = (wid >> 2) * 64;      // warp M offset within CTA tile
    int wn = (wid & 3) * 48;       // warp N offset
    int a_r = lane & 15;
    int a_k = (lane >> 4) * 16;    // bytes
    int b_r = (lane & 7) + ((lane >> 4) << 3);
    int b_k = ((lane >> 3) & 1) * 16;

    float acc[4][6][4];
#pragma unroll
    for (int mt = 0; mt < 4; mt++)
#pragma unroll
        for (int nt = 0; nt < 6; nt++)
#pragma unroll
            for (int q = 0; q < 4; q++) acc[mt][nt][q] = 0.0f;

    // ---- pipelined mainloop (3 smem stages, 1 sync per chunk) ----
    issue(0, 0);
    CP_COMMIT();
    issue(1, 1);
    CP_COMMIT();

    for (int u = 0; u < NCHUNK; u++) {
        if (u < NCHUNK - 1) { CP_WAIT(1); } else { CP_WAIT(0); }
        __syncthreads();            // chunk u resident in all threads' view

        uint32_t sb = su + SMEM_HDR + (uint32_t)(u % NSTAGE) * STAGE_BYTES;
#pragma unroll
        for (int ks = 0; ks < 4; ks++) {
            uint32_t ahi[4][4], bhi[3][4], blo[3][4];
            uint32_t kb = (uint32_t)ks * 32;
#pragma unroll
            for (int mt = 0; mt < 4; mt++) {
                uint32_t off = (uint32_t)(wm + mt * 16 + a_r) * 128 + kb + a_k;
                ldsm4(ahi[mt], sb + A_HI + sw128(off));
            }
#pragma unroll
            for (int nb = 0; nb < 3; nb++) {
                uint32_t off = (uint32_t)(wn + nb * 16 + b_r) * 128 + kb + b_k;
                ldsm4(bhi[nb], sb + B_HI + sw128(off));
            }
            // x_hi * w_hi
#pragma unroll
            for (int mt = 0; mt < 4; mt++)
#pragma unroll
                for (int nt = 0; nt < 6; nt++)
                    mma_f16(acc[mt][nt], ahi[mt], &bhi[nt >> 1][(nt & 1) * 2]);
            // x_hi * w_lo (reuse A fragments)
#pragma unroll
            for (int nb = 0; nb < 3; nb++) {
                uint32_t off = (uint32_t)(wn + nb * 16 + b_r) * 128 + kb + b_k;
                ldsm4(blo[nb], sb + B_LO + sw128(off));
            }
#pragma unroll
            for (int mt = 0; mt < 4; mt++)
#pragma unroll
                for (int nt = 0; nt < 6; nt++)
                    mma_f16(acc[mt][nt], ahi[mt], &blo[nt >> 1][(nt & 1) * 2]);
        }

        // refill the stage freed at chunk u-1 (stage (u+2)%3): all threads have
        // passed this iteration's __syncthreads, so compute of u-1 is complete.
        if (u + 2 < NCHUNK) {
            issue(u + 2, (u + 2) % NSTAGE);
            CP_COMMIT();
        }
    }

    // ---- epilogue: out[b][cout][hw] = acc + bias ----
    int pix0 = blk * MTILE + wm;
#pragma unroll
    for (int mt = 0; mt < 4; mt++) {
#pragma unroll
        for (int half = 0; half < 2; half++) {
            int p   = pix0 + mt * 16 + half * 8 + (lane >> 2);
            int b   = p / HWN;
            int hw  = p - b * HWN;
            float* ob = out + (size_t)b * COUTN * HWN + hw;
#pragma unroll
            for (int nt = 0; nt < 6; nt++) {
                int n = wn + nt * 8 + (lane & 3) * 2;
                ob[(size_t)n * HWN]       = acc[mt][nt][half * 2 + 0] + s_bias[n];
                ob[(size_t)(n + 1) * HWN] = acc[mt][nt][half * 2 + 1] + s_bias[n + 1];
            }
        }
    }
}

// ---------------- launch ----------------
extern "C" void kernel_launch(void* const* d_in, const int* in_sizes, int n_in,
                              void* d_out, int out_size) {
    const float* x    = (const float*)d_in[0];
    const float* w    = (const float*)d_in[1];
    const float* bias = (const float*)d_in[2];
    float* out        = (float*)d_out;
    (void)in_sizes; (void)n_in; (void)out_size;

    cudaFuncSetAttribute(conv_main_kernel,
                         cudaFuncAttributeMaxDynamicSharedMemorySize, SMEM_TOTAL);

    prep_w_kernel<<<(COUTN * KDIM + 255) / 256, 256>>>(w);
    prep_x_kernel<<<dim3(HWN / 32, CIN / 32, BB), 256>>>(x);
    conv_main_kernel<<<NBLK, 256, SMEM_TOTAL>>>(bias, out);
}

// round 6
// speedup vs baseline: 2.3700x; 1.6259x over previous
#include <cuda_runtime.h>
#include <cuda_fp16.h>
#include <cstdint>
#include <cstddef>

// ---------------- problem constants ----------------
#define BB     32
#define CIN    192
#define HH     56
#define WWD    56
#define HP     58
#define WP     58
#define COUTN  192
#define KDIM   1728          // CIN * 9
#define HWN    3136          // 56*56
#define NPIX   100352        // BB*HWN

// ---------------- tiling ----------------
#define MTILE   128                // pixels per CTA
#define NBLK    (NPIX / MTILE)     // 784 exactly
#define KC      64                 // K halves per chunk (128 B rows)
#define NCHUNK  27                 // 1728 / 64
#define NSTAGE  4

// smem stage layout (bytes, relative to stage base; stage base 1024-aligned)
#define A_HI    0                  // 128 x 128B = 16 KB
#define B_HI    16384              // 192 x 128B = 24 KB
#define STAGE_BYTES 40960          // 40 KB
#define SMEM_HDR    1024           // bias lives at [0..768)
#define SMEM_TOTAL  (SMEM_HDR + NSTAGE * STAGE_BYTES)   // 164864

// ---------------- device scratch (zero-initialized at module load; ----------------
// padded borders of x are never written -> stay zero, deterministic)
__device__ __align__(16) __half g_xhi[(size_t)BB * HP * WP * CIN];
__device__ __align__(16) __half g_whi[(size_t)COUTN * KDIM];

// ---------------- helpers ----------------
__device__ __forceinline__ uint32_t smem_u32(const void* p) {
    uint32_t a;
    asm("{ .reg .u64 t; cvta.to.shared.u64 t, %1; cvt.u32.u64 %0, t; }" : "=r"(a) : "l"(p));
    return a;
}

__device__ __forceinline__ uint32_t sw128(uint32_t off) {
    return off ^ ((off >> 3) & 0x70);
}

__device__ __forceinline__ void cpa16(uint32_t dst, const void* src) {
    asm volatile("cp.async.cg.shared.global [%0], [%1], 16;" :: "r"(dst), "l"(src) : "memory");
}

#define CP_COMMIT()  asm volatile("cp.async.commit_group;" ::: "memory")
#define CP_WAIT(N)   asm volatile("cp.async.wait_group %0;" :: "n"(N) : "memory")

__device__ __forceinline__ void ldsm4(uint32_t* r, uint32_t addr) {
    asm volatile("ldmatrix.sync.aligned.m8n8.x4.shared.b16 {%0,%1,%2,%3}, [%4];"
                 : "=r"(r[0]), "=r"(r[1]), "=r"(r[2]), "=r"(r[3]) : "r"(addr));
}

__device__ __forceinline__ void mma_f16(float* c, const uint32_t* a, const uint32_t* b) {
    asm volatile(
        "mma.sync.aligned.m16n8k16.row.col.f32.f16.f16.f32 "
        "{%0,%1,%2,%3}, {%4,%5,%6,%7}, {%8,%9}, {%0,%1,%2,%3};"
        : "+f"(c[0]), "+f"(c[1]), "+f"(c[2]), "+f"(c[3])
        : "r"(a[0]), "r"(a[1]), "r"(a[2]), "r"(a[3]), "r"(b[0]), "r"(b[1]));
}

// ---------------- prep kernel 1: weights -> fp16, K reordered ----------------
// new K index kn = (i*3+j)*192 + c ; old k = c*9 + (i*3+j)
__global__ void prep_w_kernel(const float* __restrict__ w) {
    int idx = blockIdx.x * 256 + threadIdx.x;
    if (idx >= COUTN * KDIM) return;
    int o  = idx / KDIM;
    int kn = idx - o * KDIM;
    int r  = kn / CIN;
    int c  = kn - r * CIN;
    g_whi[idx] = __float2half_rn(w[o * KDIM + c * 9 + r]);
}

// ---------------- prep kernel 2: x NCHW fp32 -> NHWC padded fp16 ----------------
__global__ void prep_x_kernel(const float* __restrict__ x) {
    __shared__ float tile[32][33];
    int b   = blockIdx.z;
    int hw0 = blockIdx.x * 32;
    int c0  = blockIdx.y * 32;
    int tx  = threadIdx.x & 31;
    int ty  = threadIdx.x >> 5;   // 0..7

    const float* src = x + ((size_t)b * CIN + c0) * HWN + hw0;
#pragma unroll
    for (int r = 0; r < 4; r++)
        tile[ty + r * 8][tx] = src[(size_t)(ty + r * 8) * HWN + tx];
    __syncthreads();

#pragma unroll
    for (int r = 0; r < 4; r++) {
        int hw = hw0 + ty + r * 8;
        int h  = hw / WWD;
        int w  = hw - h * WWD;
        float v = tile[tx][ty + r * 8];
        size_t dst = (((size_t)b * HP + (h + 1)) * WP + (w + 1)) * CIN + c0 + tx;
        g_xhi[dst] = __float2half_rn(v);
    }
}

// ---------------- main kernel: im2col GEMM via mma.sync (HMMA fp16) ----------------
// CTA: 128 pixels x 192 couts, 8 warps = 2(M) x 4(N), warp tile 64x48.
// Single-pass fp16 with fp32 accumulate.
__global__ void __launch_bounds__(256, 1)
conv_main_kernel(const float* __restrict__ bias, float* __restrict__ out) {
    extern __shared__ __align__(1024) char smem[];
    uint32_t su = smem_u32(smem);
    int tid  = threadIdx.x;
    int lane = tid & 31;
    int wid  = tid >> 5;
    int blk  = blockIdx.x;

    float* s_bias = (float*)smem;
    if (tid < COUTN) s_bias[tid] = bias[tid];

    // ---- per-thread cp.async geometry ----
    int vr = tid & 7;     // 16B chunk within a 128B row
    int r0 = tid >> 3;    // 0..31 row slot
    int rbase[4];
#pragma unroll
    for (int it = 0; it < 4; it++) {
        int p   = blk * MTILE + r0 + it * 32;
        int b   = p / HWN;
        int rem = p - b * HWN;
        int h   = rem / WWD;
        int w   = rem - h * WWD;
        rbase[it] = ((b * HP + h) * WP + w) * CIN;
    }

    auto issue = [&](int u, int stage) {
        int ij = u / 3;
        int c0 = (u - ij * 3) * KC;
        int i  = ij / 3;
        int j  = ij - i * 3;
        int coff = (i * WP + j) * CIN + c0;
        uint32_t sb = su + SMEM_HDR + (uint32_t)stage * STAGE_BYTES;
        // A: 128 rows x 128B
#pragma unroll
        for (int it = 0; it < 4; it++) {
            int m = r0 + it * 32;
            uint32_t sw = sw128((uint32_t)m * 128 + vr * 16);
            int go = rbase[it] + coff + vr * 8;
            cpa16(sb + A_HI + sw, g_xhi + go);
        }
        // B: 192 rows x 128B
#pragma unroll
        for (int it = 0; it < 6; it++) {
            int o = r0 + it * 32;
            uint32_t sw = sw128((uint32_t)o * 128 + vr * 16);
            size_t go = (size_t)o * KDIM + u * KC + vr * 8;
            cpa16(sb + B_HI + sw, g_whi + go);
        }
    };

    // ---- per-thread mma geometry ----
    int wm = (wid >> 2) * 64;      // warp M offset within CTA tile
    int wn = (wid & 3) * 48;       // warp N offset
    int a_r = lane & 15;
    int a_k = (lane >> 4) * 16;    // bytes
    int b_r = (lane & 7) + ((lane >> 4) << 3);
    int b_k = ((lane >> 3) & 1) * 16;

    float acc[4][6][4];
#pragma unroll
    for (int mt = 0; mt < 4; mt++)
#pragma unroll
        for (int nt = 0; nt < 6; nt++)
#pragma unroll
            for (int q = 0; q < 4; q++) acc[mt][nt][q] = 0.0f;

    // ---- pipelined mainloop (4 smem stages, issue 3 ahead, 1 sync per chunk) ----
    issue(0, 0); CP_COMMIT();
    issue(1, 1); CP_COMMIT();
    issue(2, 2); CP_COMMIT();

    for (int u = 0; u < NCHUNK; u++) {
        // groups newer than u at this point: min(NCHUNK-1, u+2) - u
        if (u < NCHUNK - 2)       { CP_WAIT(2); }
        else if (u == NCHUNK - 2) { CP_WAIT(1); }
        else                      { CP_WAIT(0); }
        __syncthreads();            // chunk u resident in all threads' view

        uint32_t sb = su + SMEM_HDR + (uint32_t)(u % NSTAGE) * STAGE_BYTES;
#pragma unroll
        for (int ks = 0; ks < 4; ks++) {
            uint32_t ahi[4][4], bhi[3][4];
            uint32_t kb = (uint32_t)ks * 32;
#pragma unroll
            for (int mt = 0; mt < 4; mt++) {
                uint32_t off = (uint32_t)(wm + mt * 16 + a_r) * 128 + kb + a_k;
                ldsm4(ahi[mt], sb + A_HI + sw128(off));
            }
#pragma unroll
            for (int nb = 0; nb < 3; nb++) {
                uint32_t off = (uint32_t)(wn + nb * 16 + b_r) * 128 + kb + b_k;
                ldsm4(bhi[nb], sb + B_HI + sw128(off));
            }
#pragma unroll
            for (int mt = 0; mt < 4; mt++)
#pragma unroll
                for (int nt = 0; nt < 6; nt++)
                    mma_f16(acc[mt][nt], ahi[mt], &bhi[nt >> 1][(nt & 1) * 2]);
        }

        // refill the stage freed at chunk u-1 (stage (u+3)%4 == (u-1)%4):
        // all threads passed this iteration's __syncthreads, so compute of
        // chunk u-1 is complete everywhere.
        if (u + 3 < NCHUNK) {
            issue(u + 3, (u + 3) % NSTAGE);
            CP_COMMIT();
        }
    }

    // ---- epilogue: out[b][cout][hw] = acc + bias ----
    int pix0 = blk * MTILE + wm;
#pragma unroll
    for (int mt = 0; mt < 4; mt++) {
#pragma unroll
        for (int half = 0; half < 2; half++) {
            int p   = pix0 + mt * 16 + half * 8 + (lane >> 2);
            int b   = p / HWN;
            int hw  = p - b * HWN;
            float* ob = out + (size_t)b * COUTN * HWN + hw;
#pragma unroll
            for (int nt = 0; nt < 6; nt++) {
                int n = wn + nt * 8 + (lane & 3) * 2;
                ob[(size_t)n * HWN]       = acc[mt][nt][half * 2 + 0] + s_bias[n];
                ob[(size_t)(n + 1) * HWN] = acc[mt][nt][half * 2 + 1] + s_bias[n + 1];
            }
        }
    }
}

// ---------------- launch ----------------
extern "C" void kernel_launch(void* const* d_in, const int* in_sizes, int n_in,
                              void* d_out, int out_size) {
    const float* x    = (const float*)d_in[0];
    const float* w    = (const float*)d_in[1];
    const float* bias = (const float*)d_in[2];
    float* out        = (float*)d_out;
    (void)in_sizes; (void)n_in; (void)out_size;

    cudaFuncSetAttribute(conv_main_kernel,
                         cudaFuncAttributeMaxDynamicSharedMemorySize, SMEM_TOTAL);

    prep_w_kernel<<<(COUTN * KDIM + 255) / 256, 256>>>(w);
    prep_x_kernel<<<dim3(HWN / 32, CIN / 32, BB), 256>>>(x);
    conv_main_kernel<<<NBLK, 256, SMEM_TOTAL>>>(bias, out);
}